// round 3
// baseline (speedup 1.0000x reference)
#include <cuda_runtime.h>
#include <cuda_bf16.h>
#include <cuda_fp16.h>
#include <stdint.h>

#define N_TOK   8192
#define HIDDEN  1024
#define LATENT  16384
#define TOPK    32
#define NCAND   64

// ---------------- static device scratch (no allocations allowed) ----------------
__device__ __nv_bfloat16 g_xb[(size_t)N_TOK * HIDDEN];     // 16 MB
__device__ __nv_bfloat16 g_wb[(size_t)LATENT * HIDDEN];    // 32 MB
__device__ __half        g_z [(size_t)N_TOK * LATENT];     // 256 MB
__device__ int           g_cand[(size_t)N_TOK * NCAND];    // 2 MB
__device__ int           g_tidx[(size_t)N_TOK * TOPK];
__device__ float         g_tval[(size_t)N_TOK * TOPK];
__device__ float         g_wdt[(size_t)LATENT * HIDDEN];   // 64 MB (W_dec transposed)

// ---------------- fp32 -> bf16 converts ----------------
__global__ void cvt_x_kernel(const float4* __restrict__ src, int n4) {
    int i = blockIdx.x * blockDim.x + threadIdx.x;
    if (i >= n4) return;
    float4 f = src[i];
    __nv_bfloat162 h0 = __floats2bfloat162_rn(f.x, f.y);
    __nv_bfloat162 h1 = __floats2bfloat162_rn(f.z, f.w);
    uint2 o; o.x = *(const uint32_t*)&h0; o.y = *(const uint32_t*)&h1;
    *(uint2*)&g_xb[(size_t)i * 4] = o;
}
__global__ void cvt_w_kernel(const float4* __restrict__ src, int n4) {
    int i = blockIdx.x * blockDim.x + threadIdx.x;
    if (i >= n4) return;
    float4 f = src[i];
    __nv_bfloat162 h0 = __floats2bfloat162_rn(f.x, f.y);
    __nv_bfloat162 h1 = __floats2bfloat162_rn(f.z, f.w);
    uint2 o; o.x = *(const uint32_t*)&h0; o.y = *(const uint32_t*)&h1;
    *(uint2*)&g_wb[(size_t)i * 4] = o;
}

// ---------------- encode GEMM: z = x @ W_enc^T (bf16 HMMA, fp32 accum, fp16 store) -----
// cp.async 4-stage pipeline, one __syncthreads per K-tile.
#define BM 128
#define BN 256
#define BK 32
#define KD HIDDEN
#define LDAS 40            // BK + 8 pad (80B rows: ldmatrix conflict-free, 16B aligned)
#define NSTG 4
#define SA_ELEMS (BM * LDAS)            // 5120
#define SB_ELEMS (BN * LDAS)            // 10240
#define STG_ELEMS (SA_ELEMS + SB_ELEMS) // 15360 bf16 = 30720 B/stage

__device__ __forceinline__ void cp_async16(uint32_t smem_dst, const void* gptr) {
    asm volatile("cp.async.cg.shared.global [%0], [%1], 16;"
                 :: "r"(smem_dst), "l"(gptr));
}
__device__ __forceinline__ void cp_commit() {
    asm volatile("cp.async.commit_group;");
}
template <int N>
__device__ __forceinline__ void cp_wait() {
    asm volatile("cp.async.wait_group %0;" :: "n"(N));
}

__global__ void __launch_bounds__(512, 1)
gemm_enc_kernel() {
    extern __shared__ __nv_bfloat16 sm[];

    const int tid  = threadIdx.x;
    const int lane = tid & 31;
    const int warp = tid >> 5;
    const int wr = warp >> 2;        // 0..3 -> 32 rows each
    const int wc = warp & 3;         // 0..3 -> 64 cols each
    const int bm = blockIdx.y * BM;
    const int bn = blockIdx.x * BN;

    // global->shared mapping: one 16B cp.async per row-slice
    const int gr = tid >> 2;         // 0..127
    const int gc = (tid & 3) * 8;    // 0,8,16,24

    const __nv_bfloat16* Ag = g_xb + (size_t)(bm + gr) * KD + gc;
    const __nv_bfloat16* Bg0 = g_wb + (size_t)(bn + gr) * KD + gc;
    const __nv_bfloat16* Bg1 = g_wb + (size_t)(bn + gr + 128) * KD + gc;

    const uint32_t smemBase = (uint32_t)__cvta_generic_to_shared(sm);
    const uint32_t dA_off  = (uint32_t)(gr * LDAS + gc) * 2;
    const uint32_t dB0_off = (uint32_t)(SA_ELEMS + gr * LDAS + gc) * 2;
    const uint32_t dB1_off = (uint32_t)(SA_ELEMS + (gr + 128) * LDAS + gc) * 2;

    float acc[2][8][4];
    #pragma unroll
    for (int i = 0; i < 2; i++)
        #pragma unroll
        for (int j = 0; j < 8; j++)
            #pragma unroll
            for (int q = 0; q < 4; q++) acc[i][j][q] = 0.f;

    const int NKT = KD / BK;   // 32

    // prologue: issue NSTG-1 stages
    #pragma unroll
    for (int kt = 0; kt < NSTG - 1; ++kt) {
        const uint32_t stg = smemBase + (kt % NSTG) * STG_ELEMS * 2;
        const int ko = kt * BK;
        cp_async16(stg + dA_off,  Ag  + ko);
        cp_async16(stg + dB0_off, Bg0 + ko);
        cp_async16(stg + dB1_off, Bg1 + ko);
        cp_commit();
    }

    for (int kt = 0; kt < NKT; ++kt) {
        cp_wait<NSTG - 2>();
        __syncthreads();

        // issue loads for stage kt+NSTG-1 (overwrites stage consumed at kt-1)
        if (kt + NSTG - 1 < NKT) {
            const uint32_t stg = smemBase + ((kt + NSTG - 1) % NSTG) * STG_ELEMS * 2;
            const int ko = (kt + NSTG - 1) * BK;
            cp_async16(stg + dA_off,  Ag  + ko);
            cp_async16(stg + dB0_off, Bg0 + ko);
            cp_async16(stg + dB1_off, Bg1 + ko);
        }
        cp_commit();   // commit every iteration to keep group accounting uniform

        const uint32_t cur = smemBase + (kt % NSTG) * STG_ELEMS * 2;
        const uint32_t aBase = cur;
        const uint32_t bBase = cur + SA_ELEMS * 2;

        #pragma unroll
        for (int ks = 0; ks < 2; ++ks) {
            const int kb = ks * 16;
            uint32_t afr[2][4];
            #pragma unroll
            for (int mi = 0; mi < 2; ++mi) {
                int row = wr * 32 + mi * 16 + (lane & 15);
                int col = kb + ((lane >> 4) << 3);
                uint32_t addr = aBase + (uint32_t)(row * LDAS + col) * 2;
                asm volatile("ldmatrix.sync.aligned.m8n8.x4.shared.b16 {%0,%1,%2,%3}, [%4];"
                    : "=r"(afr[mi][0]), "=r"(afr[mi][1]), "=r"(afr[mi][2]), "=r"(afr[mi][3])
                    : "r"(addr));
            }
            uint32_t bfr[8][2];
            #pragma unroll
            for (int j = 0; j < 4; ++j) {
                int n = wc * 64 + j * 16 + ((lane >> 4) << 3) + (lane & 7);
                int col = kb + (lane & 8);
                uint32_t addr = bBase + (uint32_t)(n * LDAS + col) * 2;
                asm volatile("ldmatrix.sync.aligned.m8n8.x4.shared.b16 {%0,%1,%2,%3}, [%4];"
                    : "=r"(bfr[2*j][0]), "=r"(bfr[2*j][1]), "=r"(bfr[2*j+1][0]), "=r"(bfr[2*j+1][1])
                    : "r"(addr));
            }
            #pragma unroll
            for (int mi = 0; mi < 2; ++mi)
                #pragma unroll
                for (int ni = 0; ni < 8; ++ni) {
                    asm volatile(
                        "mma.sync.aligned.m16n8k16.row.col.f32.bf16.bf16.f32 "
                        "{%0,%1,%2,%3},{%4,%5,%6,%7},{%8,%9},{%0,%1,%2,%3};"
                        : "+f"(acc[mi][ni][0]), "+f"(acc[mi][ni][1]),
                          "+f"(acc[mi][ni][2]), "+f"(acc[mi][ni][3])
                        : "r"(afr[mi][0]), "r"(afr[mi][1]), "r"(afr[mi][2]), "r"(afr[mi][3]),
                          "r"(bfr[ni][0]), "r"(bfr[ni][1]));
                }
        }
        __syncthreads();
    }

    // epilogue: fp32 acc -> fp16 z
    const int grp = lane >> 2;
    const int qc  = (lane & 3) * 2;
    #pragma unroll
    for (int mi = 0; mi < 2; ++mi)
        #pragma unroll
        for (int ni = 0; ni < 8; ++ni) {
            int r0 = bm + wr * 32 + mi * 16 + grp;
            int c0 = bn + wc * 64 + ni * 8 + qc;
            __half2 h01 = __floats2half2_rn(acc[mi][ni][0], acc[mi][ni][1]);
            __half2 h23 = __floats2half2_rn(acc[mi][ni][2], acc[mi][ni][3]);
            *(__half2*)&g_z[(size_t)r0 * LATENT + c0] = h01;
            *(__half2*)&g_z[(size_t)(r0 + 8) * LATENT + c0] = h23;
        }
}

// ---------------- per-row top-64 candidates via 2-pass radix histogram on fp16 keys ----------------
__global__ void __launch_bounds__(256)
topk_cand_kernel() {
    __shared__ unsigned short keys[LATENT];          // 32 KB
    __shared__ unsigned int hist[256];
    __shared__ int s_b, s_k2;
    __shared__ unsigned int s_T;
    __shared__ int s_cnt;
    __shared__ int cand[NCAND];

    const int row = blockIdx.x;
    const int tid = threadIdx.x;
    if (tid < 256) hist[tid] = 0;
    if (tid == 0) s_cnt = 0;
    __syncthreads();

    const uint4* zr = (const uint4*)(g_z + (size_t)row * LATENT);
    for (int i = tid; i < LATENT / 8; i += 256) {
        uint4 v = zr[i];
        uint32_t w[4] = {v.x, v.y, v.z, v.w};
        #pragma unroll
        for (int q = 0; q < 4; ++q) {
            #pragma unroll
            for (int p = 0; p < 2; ++p) {
                unsigned short h = (unsigned short)((w[q] >> (16 * p)) & 0xFFFFu);
                unsigned short key = (h & 0x8000u) ? (unsigned short)(~h)
                                                   : (unsigned short)(h | 0x8000u);
                keys[i * 8 + q * 2 + p] = key;
                atomicAdd(&hist[key >> 8], 1u);
            }
        }
    }
    __syncthreads();
    if (tid == 0) {
        unsigned int c = 0; int b = 255;
        for (; b >= 0; --b) { c += hist[b]; if (c >= NCAND) break; }
        s_b  = b;
        s_k2 = NCAND - (int)(c - hist[b]);
    }
    __syncthreads();
    const int bsel = s_b, k2 = s_k2;
    if (tid < 256) hist[tid] = 0;
    __syncthreads();
    for (int i = tid; i < LATENT; i += 256) {
        unsigned short key = keys[i];
        if ((key >> 8) == (unsigned)bsel) atomicAdd(&hist[key & 255], 1u);
    }
    __syncthreads();
    if (tid == 0) {
        unsigned int c = 0; int l = 255;
        for (; l >= 0; --l) { c += hist[l]; if ((int)c >= k2) break; }
        s_T = ((unsigned)bsel << 8) | (unsigned)l;
    }
    __syncthreads();
    const unsigned int T = s_T;
    for (int i = tid; i < LATENT; i += 256) {
        if ((unsigned int)keys[i] > T) {
            int p = atomicAdd(&s_cnt, 1);
            cand[p] = i;
        }
    }
    __syncthreads();
    for (int i = tid; i < LATENT; i += 256) {
        if ((unsigned int)keys[i] == T) {
            int p = atomicAdd(&s_cnt, 1);
            if (p < NCAND) cand[p] = i;
        }
    }
    __syncthreads();
    if (tid < NCAND) g_cand[(size_t)row * NCAND + tid] = cand[tid];
}

// ---------------- exact fp32 recompute of 64 candidate dots + exact top-32 + scatter ----------------
__global__ void __launch_bounds__(256)
exact_topk_kernel(const float* __restrict__ x, const float* __restrict__ Wenc,
                  float* __restrict__ s_out) {
    __shared__ __align__(16) float xs[HIDDEN];
    __shared__ float vals[NCAND];
    __shared__ int   cand[NCAND];
    const int row  = blockIdx.x;
    const int tid  = threadIdx.x;
    const int lane = tid & 31;
    const int warp = tid >> 5;

    const float4* xr = (const float4*)(x + (size_t)row * HIDDEN);
    *(float4*)&xs[tid * 4] = xr[tid];
    if (tid < NCAND) cand[tid] = g_cand[(size_t)row * NCAND + tid];
    __syncthreads();

    for (int c = warp; c < NCAND; c += 8) {
        const float4* wrow = (const float4*)(Wenc + (size_t)cand[c] * HIDDEN);
        float a = 0.f;
        #pragma unroll
        for (int j = 0; j < 8; ++j) {
            float4 w4 = wrow[lane + 32 * j];
            float4 x4 = *(const float4*)&xs[(lane + 32 * j) * 4];
            a += w4.x * x4.x + w4.y * x4.y + w4.z * x4.z + w4.w * x4.w;
        }
        #pragma unroll
        for (int o = 16; o; o >>= 1) a += __shfl_xor_sync(0xffffffffu, a, o);
        if (lane == 0) vals[c] = a;
    }
    __syncthreads();

    if (warp == 0) {
        float v0 = vals[lane], v1 = vals[lane + 32];
        for (int t = 0; t < TOPK; ++t) {
            float lv = v0; int li = lane;
            if (v1 > lv) { lv = v1; li = lane + 32; }
            #pragma unroll
            for (int o = 16; o; o >>= 1) {
                float ov = __shfl_xor_sync(0xffffffffu, lv, o);
                int   oi = __shfl_xor_sync(0xffffffffu, li, o);
                if (ov > lv || (ov == lv && oi < li)) { lv = ov; li = oi; }
            }
            if (lane == 0) {
                int ci = cand[li];
                float rv = lv > 0.f ? lv : 0.f;
                s_out[(size_t)row * LATENT + ci] = rv;
                g_tidx[(size_t)row * TOPK + t] = ci;
                g_tval[(size_t)row * TOPK + t] = rv;
            }
            if ((li & 31) == lane) { if (li < 32) v0 = -1e30f; else v1 = -1e30f; }
        }
    }
}

// ---------------- W_dec transpose: [1024][16384] -> [16384][1024] ----------------
__global__ void transpose_wdec_kernel(const float* __restrict__ W) {
    __shared__ float t[32][33];
    const int bl = blockIdx.x * 32;   // latent
    const int bh = blockIdx.y * 32;   // hidden
    const int tx = threadIdx.x, ty = threadIdx.y;
    #pragma unroll
    for (int j = 0; j < 4; ++j)
        t[ty + 8 * j][tx] = W[(size_t)(bh + ty + 8 * j) * LATENT + bl + tx];
    __syncthreads();
    #pragma unroll
    for (int j = 0; j < 4; ++j)
        g_wdt[(size_t)(bl + ty + 8 * j) * HIDDEN + bh + tx] = t[tx][ty + 8 * j];
}

// ---------------- sparse decode: x_hat[n] = sum_k val_k * W_decT[idx_k] ----------------
__global__ void __launch_bounds__(256)
decode_kernel(float* __restrict__ xhat) {
    __shared__ int   sidx[TOPK];
    __shared__ float sval[TOPK];
    const int row = blockIdx.x;
    const int tid = threadIdx.x;
    if (tid < TOPK) {
        sidx[tid] = g_tidx[(size_t)row * TOPK + tid];
        sval[tid] = g_tval[(size_t)row * TOPK + tid];
    }
    __syncthreads();
    float a0 = 0.f, a1 = 0.f, a2 = 0.f, a3 = 0.f;
    #pragma unroll 4
    for (int k = 0; k < TOPK; ++k) {
        const float* wt = g_wdt + (size_t)sidx[k] * HIDDEN;
        float v = sval[k];
        a0 += v * wt[tid];
        a1 += v * wt[tid + 256];
        a2 += v * wt[tid + 512];
        a3 += v * wt[tid + 768];
    }
    float* o = xhat + (size_t)row * HIDDEN;
    o[tid] = a0; o[tid + 256] = a1; o[tid + 512] = a2; o[tid + 768] = a3;
}

// ---------------- launch ----------------
extern "C" void kernel_launch(void* const* d_in, const int* in_sizes, int n_in,
                              void* d_out, int out_size) {
    const float* x     = (const float*)d_in[0];
    const float* W_enc = (const float*)d_in[1];
    const float* W_dec = (const float*)d_in[2];
    float* xhat = (float*)d_out;
    float* s    = (float*)d_out + (size_t)N_TOK * HIDDEN;

    const int smem_gemm = NSTG * STG_ELEMS * 2;     // 122880 B
    cudaFuncSetAttribute(gemm_enc_kernel, cudaFuncAttributeMaxDynamicSharedMemorySize, smem_gemm);

    // converts
    cvt_x_kernel<<<(N_TOK * HIDDEN / 4 + 255) / 256, 256>>>((const float4*)x, N_TOK * HIDDEN / 4);
    cvt_w_kernel<<<(LATENT * HIDDEN / 4 + 255) / 256, 256>>>((const float4*)W_enc, LATENT * HIDDEN / 4);

    // W_dec transpose (independent; needed before decode)
    transpose_wdec_kernel<<<dim3(LATENT / 32, HIDDEN / 32), dim3(32, 8)>>>(W_dec);

    // zero the sparse output region (scatter fills only top-k slots)
    cudaMemsetAsync(s, 0, (size_t)N_TOK * LATENT * sizeof(float), 0);

    // encode GEMM (bf16 candidates)
    gemm_enc_kernel<<<dim3(LATENT / BN, N_TOK / BM), 512, smem_gemm>>>();

    // top-64 candidates per row
    topk_cand_kernel<<<N_TOK, 256>>>();

    // exact fp32 recompute + top-32 select + scatter into s
    exact_topk_kernel<<<N_TOK, 256>>>(x, W_enc, s);

    // sparse decode
    decode_kernel<<<N_TOK, 256>>>(xhat);
}

// round 4
// speedup vs baseline: 1.0995x; 1.0995x over previous
#include <cuda_runtime.h>
#include <cuda_bf16.h>
#include <cuda_fp16.h>
#include <stdint.h>

#define N_TOK   8192
#define HIDDEN  1024
#define LATENT  16384
#define TOPK    32
#define NCAND   64

// ---------------- static device scratch (no allocations allowed) ----------------
__device__ __nv_bfloat16 g_xb[(size_t)N_TOK * HIDDEN];     // 16 MB
__device__ __nv_bfloat16 g_wb[(size_t)LATENT * HIDDEN];    // 32 MB
__device__ __half        g_z [(size_t)N_TOK * LATENT];     // 256 MB
__device__ int           g_cand[(size_t)N_TOK * NCAND];    // 2 MB
__device__ int           g_tidx[(size_t)N_TOK * TOPK];
__device__ float         g_tval[(size_t)N_TOK * TOPK];
__device__ float         g_wdt[(size_t)LATENT * HIDDEN];   // 64 MB (W_dec transposed)

// ---------------- fp32 -> bf16 converts ----------------
__global__ void cvt_x_kernel(const float4* __restrict__ src, int n4) {
    int i = blockIdx.x * blockDim.x + threadIdx.x;
    if (i >= n4) return;
    float4 f = src[i];
    __nv_bfloat162 h0 = __floats2bfloat162_rn(f.x, f.y);
    __nv_bfloat162 h1 = __floats2bfloat162_rn(f.z, f.w);
    uint2 o; o.x = *(const uint32_t*)&h0; o.y = *(const uint32_t*)&h1;
    *(uint2*)&g_xb[(size_t)i * 4] = o;
}
__global__ void cvt_w_kernel(const float4* __restrict__ src, int n4) {
    int i = blockIdx.x * blockDim.x + threadIdx.x;
    if (i >= n4) return;
    float4 f = src[i];
    __nv_bfloat162 h0 = __floats2bfloat162_rn(f.x, f.y);
    __nv_bfloat162 h1 = __floats2bfloat162_rn(f.z, f.w);
    uint2 o; o.x = *(const uint32_t*)&h0; o.y = *(const uint32_t*)&h1;
    *(uint2*)&g_wb[(size_t)i * 4] = o;
}

// ---------------- encode GEMM: z = x @ W_enc^T (bf16 HMMA, fp32 accum, fp16 store) -----
// 128x128 CTA tile, 256 threads, 2 CTAs/SM, BK=64, 3-stage cp.async, ONE barrier/K-tile.
#define BM 128
#define BN 128
#define BK 64
#define KD HIDDEN
#define LDAS 72                          // 64 + 8 pad elems (144B rows, LDSM conflict-free)
#define NSTG 3
#define SA_ELEMS (BM * LDAS)             // 9216
#define SB_ELEMS (BN * LDAS)             // 9216
#define STG_ELEMS (SA_ELEMS + SB_ELEMS)  // 18432 bf16 = 36864 B/stage
#define GEMM_SMEM (NSTG * STG_ELEMS * 2) // 110592 B

__device__ __forceinline__ void cp_async16(uint32_t smem_dst, const void* gptr) {
    asm volatile("cp.async.cg.shared.global [%0], [%1], 16;"
                 :: "r"(smem_dst), "l"(gptr));
}
__device__ __forceinline__ void cp_commit() {
    asm volatile("cp.async.commit_group;");
}
template <int N>
__device__ __forceinline__ void cp_wait() {
    asm volatile("cp.async.wait_group %0;" :: "n"(N));
}

__global__ void __launch_bounds__(256, 2)
gemm_enc_kernel() {
    extern __shared__ __nv_bfloat16 sm[];

    const int tid  = threadIdx.x;
    const int lane = tid & 31;
    const int warp = tid >> 5;
    const int wr = warp >> 2;        // 0..1 -> 64 rows each
    const int wc = warp & 3;         // 0..3 -> 32 cols each
    const int bm = blockIdx.y * BM;
    const int bn = blockIdx.x * BN;

    // cp.async mapping: chunk c = tid + 256*j (j=0..3); row=c>>3, col=(c&7)*8
    const int gr = tid >> 3;             // base row 0..31 (j adds 32 each)
    const int gc = (tid & 7) * 8;

    const __nv_bfloat16* Ag = g_xb + (size_t)(bm + gr) * KD + gc;
    const __nv_bfloat16* Bg = g_wb + (size_t)(bn + gr) * KD + gc;

    const uint32_t smemBase = (uint32_t)__cvta_generic_to_shared(sm);
    uint32_t dA[4], dB[4];
    #pragma unroll
    for (int j = 0; j < 4; ++j) {
        dA[j] = (uint32_t)(((gr + 32 * j) * LDAS + gc) * 2);
        dB[j] = (uint32_t)((SA_ELEMS + (gr + 32 * j) * LDAS + gc) * 2);
    }

    float acc[4][4][4];
    #pragma unroll
    for (int i = 0; i < 4; i++)
        #pragma unroll
        for (int j = 0; j < 4; j++)
            #pragma unroll
            for (int q = 0; q < 4; q++) acc[i][j][q] = 0.f;

    const int NKT = KD / BK;   // 16

    // prologue: issue NSTG-1 stages
    #pragma unroll
    for (int kt = 0; kt < NSTG - 1; ++kt) {
        const uint32_t stg = smemBase + kt * STG_ELEMS * 2;
        const int ko = kt * BK;
        #pragma unroll
        for (int j = 0; j < 4; ++j) {
            cp_async16(stg + dA[j], Ag + (size_t)(32 * j) * KD + ko);
            cp_async16(stg + dB[j], Bg + (size_t)(32 * j) * KD + ko);
        }
        cp_commit();
    }

    for (int kt = 0; kt < NKT; ++kt) {
        cp_wait<NSTG - 2>();
        __syncthreads();   // stage kt ready; all reads of the buffer we now overwrite are done

        // issue loads for stage kt+NSTG-1 (same buffer that was read at iter kt-1)
        if (kt + NSTG - 1 < NKT) {
            const uint32_t stg = smemBase + ((kt + NSTG - 1) % NSTG) * STG_ELEMS * 2;
            const int ko = (kt + NSTG - 1) * BK;
            #pragma unroll
            for (int j = 0; j < 4; ++j) {
                cp_async16(stg + dA[j], Ag + (size_t)(32 * j) * KD + ko);
                cp_async16(stg + dB[j], Bg + (size_t)(32 * j) * KD + ko);
            }
        }
        cp_commit();   // uniform group accounting

        const uint32_t cur = smemBase + (kt % NSTG) * STG_ELEMS * 2;
        const uint32_t aBase = cur;
        const uint32_t bBase = cur + SA_ELEMS * 2;

        #pragma unroll
        for (int ks = 0; ks < 4; ++ks) {
            const int kb = ks * 16;
            uint32_t afr[4][4];
            #pragma unroll
            for (int mi = 0; mi < 4; ++mi) {
                int row = wr * 64 + mi * 16 + (lane & 15);
                int col = kb + ((lane >> 4) << 3);
                uint32_t addr = aBase + (uint32_t)(row * LDAS + col) * 2;
                asm volatile("ldmatrix.sync.aligned.m8n8.x4.shared.b16 {%0,%1,%2,%3}, [%4];"
                    : "=r"(afr[mi][0]), "=r"(afr[mi][1]), "=r"(afr[mi][2]), "=r"(afr[mi][3])
                    : "r"(addr));
            }
            uint32_t bfr[4][2];
            #pragma unroll
            for (int j = 0; j < 2; ++j) {
                int n = wc * 32 + j * 16 + ((lane >> 4) << 3) + (lane & 7);
                int col = kb + (lane & 8);
                uint32_t addr = bBase + (uint32_t)(n * LDAS + col) * 2;
                asm volatile("ldmatrix.sync.aligned.m8n8.x4.shared.b16 {%0,%1,%2,%3}, [%4];"
                    : "=r"(bfr[2*j][0]), "=r"(bfr[2*j][1]), "=r"(bfr[2*j+1][0]), "=r"(bfr[2*j+1][1])
                    : "r"(addr));
            }
            #pragma unroll
            for (int mi = 0; mi < 4; ++mi)
                #pragma unroll
                for (int ni = 0; ni < 4; ++ni) {
                    asm volatile(
                        "mma.sync.aligned.m16n8k16.row.col.f32.bf16.bf16.f32 "
                        "{%0,%1,%2,%3},{%4,%5,%6,%7},{%8,%9},{%0,%1,%2,%3};"
                        : "+f"(acc[mi][ni][0]), "+f"(acc[mi][ni][1]),
                          "+f"(acc[mi][ni][2]), "+f"(acc[mi][ni][3])
                        : "r"(afr[mi][0]), "r"(afr[mi][1]), "r"(afr[mi][2]), "r"(afr[mi][3]),
                          "r"(bfr[ni][0]), "r"(bfr[ni][1]));
                }
        }
    }

    // epilogue: fp32 acc -> fp16 z
    const int grp = lane >> 2;
    const int qc  = (lane & 3) * 2;
    #pragma unroll
    for (int mi = 0; mi < 4; ++mi)
        #pragma unroll
        for (int ni = 0; ni < 4; ++ni) {
            int r0 = bm + wr * 64 + mi * 16 + grp;
            int c0 = bn + wc * 32 + ni * 8 + qc;
            __half2 h01 = __floats2half2_rn(acc[mi][ni][0], acc[mi][ni][1]);
            __half2 h23 = __floats2half2_rn(acc[mi][ni][2], acc[mi][ni][3]);
            *(__half2*)&g_z[(size_t)r0 * LATENT + c0] = h01;
            *(__half2*)&g_z[(size_t)(r0 + 8) * LATENT + c0] = h23;
        }
}

// ---------------- per-row top-64 candidates via 2-pass radix histogram on fp16 keys ----------------
__global__ void __launch_bounds__(256)
topk_cand_kernel() {
    __shared__ unsigned short keys[LATENT];          // 32 KB
    __shared__ unsigned int hist[256];
    __shared__ int s_b, s_k2;
    __shared__ unsigned int s_T;
    __shared__ int s_cnt;
    __shared__ int cand[NCAND];

    const int row = blockIdx.x;
    const int tid = threadIdx.x;
    if (tid < 256) hist[tid] = 0;
    if (tid == 0) s_cnt = 0;
    __syncthreads();

    const uint4* zr = (const uint4*)(g_z + (size_t)row * LATENT);
    for (int i = tid; i < LATENT / 8; i += 256) {
        uint4 v = zr[i];
        uint32_t w[4] = {v.x, v.y, v.z, v.w};
        #pragma unroll
        for (int q = 0; q < 4; ++q) {
            #pragma unroll
            for (int p = 0; p < 2; ++p) {
                unsigned short h = (unsigned short)((w[q] >> (16 * p)) & 0xFFFFu);
                unsigned short key = (h & 0x8000u) ? (unsigned short)(~h)
                                                   : (unsigned short)(h | 0x8000u);
                keys[i * 8 + q * 2 + p] = key;
                atomicAdd(&hist[key >> 8], 1u);
            }
        }
    }
    __syncthreads();
    if (tid == 0) {
        unsigned int c = 0; int b = 255;
        for (; b >= 0; --b) { c += hist[b]; if (c >= NCAND) break; }
        s_b  = b;
        s_k2 = NCAND - (int)(c - hist[b]);
    }
    __syncthreads();
    const int bsel = s_b, k2 = s_k2;
    if (tid < 256) hist[tid] = 0;
    __syncthreads();
    for (int i = tid; i < LATENT; i += 256) {
        unsigned short key = keys[i];
        if ((key >> 8) == (unsigned)bsel) atomicAdd(&hist[key & 255], 1u);
    }
    __syncthreads();
    if (tid == 0) {
        unsigned int c = 0; int l = 255;
        for (; l >= 0; --l) { c += hist[l]; if ((int)c >= k2) break; }
        s_T = ((unsigned)bsel << 8) | (unsigned)l;
    }
    __syncthreads();
    const unsigned int T = s_T;
    for (int i = tid; i < LATENT; i += 256) {
        if ((unsigned int)keys[i] > T) {
            int p = atomicAdd(&s_cnt, 1);
            cand[p] = i;
        }
    }
    __syncthreads();
    for (int i = tid; i < LATENT; i += 256) {
        if ((unsigned int)keys[i] == T) {
            int p = atomicAdd(&s_cnt, 1);
            if (p < NCAND) cand[p] = i;
        }
    }
    __syncthreads();
    if (tid < NCAND) g_cand[(size_t)row * NCAND + tid] = cand[tid];
}

// ---------------- exact fp32 recompute of 64 candidate dots + exact top-32 + scatter ----------------
__global__ void __launch_bounds__(256)
exact_topk_kernel(const float* __restrict__ x, const float* __restrict__ Wenc,
                  float* __restrict__ s_out) {
    __shared__ __align__(16) float xs[HIDDEN];
    __shared__ float vals[NCAND];
    __shared__ int   cand[NCAND];
    const int row  = blockIdx.x;
    const int tid  = threadIdx.x;
    const int lane = tid & 31;
    const int warp = tid >> 5;

    const float4* xr = (const float4*)(x + (size_t)row * HIDDEN);
    *(float4*)&xs[tid * 4] = xr[tid];
    if (tid < NCAND) cand[tid] = g_cand[(size_t)row * NCAND + tid];
    __syncthreads();

    for (int c = warp; c < NCAND; c += 8) {
        const float4* wrow = (const float4*)(Wenc + (size_t)cand[c] * HIDDEN);
        float a = 0.f;
        #pragma unroll
        for (int j = 0; j < 8; ++j) {
            float4 w4 = wrow[lane + 32 * j];
            float4 x4 = *(const float4*)&xs[(lane + 32 * j) * 4];
            a += w4.x * x4.x + w4.y * x4.y + w4.z * x4.z + w4.w * x4.w;
        }
        #pragma unroll
        for (int o = 16; o; o >>= 1) a += __shfl_xor_sync(0xffffffffu, a, o);
        if (lane == 0) vals[c] = a;
    }
    __syncthreads();

    if (warp == 0) {
        float v0 = vals[lane], v1 = vals[lane + 32];
        for (int t = 0; t < TOPK; ++t) {
            float lv = v0; int li = lane;
            if (v1 > lv) { lv = v1; li = lane + 32; }
            #pragma unroll
            for (int o = 16; o; o >>= 1) {
                float ov = __shfl_xor_sync(0xffffffffu, lv, o);
                int   oi = __shfl_xor_sync(0xffffffffu, li, o);
                if (ov > lv || (ov == lv && oi < li)) { lv = ov; li = oi; }
            }
            if (lane == 0) {
                int ci = cand[li];
                float rv = lv > 0.f ? lv : 0.f;
                s_out[(size_t)row * LATENT + ci] = rv;
                g_tidx[(size_t)row * TOPK + t] = ci;
                g_tval[(size_t)row * TOPK + t] = rv;
            }
            if ((li & 31) == lane) { if (li < 32) v0 = -1e30f; else v1 = -1e30f; }
        }
    }
}

// ---------------- W_dec transpose: [1024][16384] -> [16384][1024] ----------------
__global__ void transpose_wdec_kernel(const float* __restrict__ W) {
    __shared__ float t[32][33];
    const int bl = blockIdx.x * 32;   // latent
    const int bh = blockIdx.y * 32;   // hidden
    const int tx = threadIdx.x, ty = threadIdx.y;
    #pragma unroll
    for (int j = 0; j < 4; ++j)
        t[ty + 8 * j][tx] = W[(size_t)(bh + ty + 8 * j) * LATENT + bl + tx];
    __syncthreads();
    #pragma unroll
    for (int j = 0; j < 4; ++j)
        g_wdt[(size_t)(bl + ty + 8 * j) * HIDDEN + bh + tx] = t[tx][ty + 8 * j];
}

// ---------------- sparse decode: x_hat[n] = sum_k val_k * W_decT[idx_k] ----------------
__global__ void __launch_bounds__(256)
decode_kernel(float* __restrict__ xhat) {
    __shared__ int   sidx[TOPK];
    __shared__ float sval[TOPK];
    const int row = blockIdx.x;
    const int tid = threadIdx.x;
    if (tid < TOPK) {
        sidx[tid] = g_tidx[(size_t)row * TOPK + tid];
        sval[tid] = g_tval[(size_t)row * TOPK + tid];
    }
    __syncthreads();
    float a0 = 0.f, a1 = 0.f, a2 = 0.f, a3 = 0.f;
    #pragma unroll 4
    for (int k = 0; k < TOPK; ++k) {
        const float* wt = g_wdt + (size_t)sidx[k] * HIDDEN;
        float v = sval[k];
        a0 += v * wt[tid];
        a1 += v * wt[tid + 256];
        a2 += v * wt[tid + 512];
        a3 += v * wt[tid + 768];
    }
    float* o = xhat + (size_t)row * HIDDEN;
    o[tid] = a0; o[tid + 256] = a1; o[tid + 512] = a2; o[tid + 768] = a3;
}

// ---------------- launch ----------------
extern "C" void kernel_launch(void* const* d_in, const int* in_sizes, int n_in,
                              void* d_out, int out_size) {
    const float* x     = (const float*)d_in[0];
    const float* W_enc = (const float*)d_in[1];
    const float* W_dec = (const float*)d_in[2];
    float* xhat = (float*)d_out;
    float* s    = (float*)d_out + (size_t)N_TOK * HIDDEN;

    cudaFuncSetAttribute(gemm_enc_kernel, cudaFuncAttributeMaxDynamicSharedMemorySize, GEMM_SMEM);

    // converts
    cvt_x_kernel<<<(N_TOK * HIDDEN / 4 + 255) / 256, 256>>>((const float4*)x, N_TOK * HIDDEN / 4);
    cvt_w_kernel<<<(LATENT * HIDDEN / 4 + 255) / 256, 256>>>((const float4*)W_enc, LATENT * HIDDEN / 4);

    // W_dec transpose (independent; needed before decode)
    transpose_wdec_kernel<<<dim3(LATENT / 32, HIDDEN / 32), dim3(32, 8)>>>(W_dec);

    // zero the sparse output region (scatter fills only top-k slots)
    cudaMemsetAsync(s, 0, (size_t)N_TOK * LATENT * sizeof(float), 0);

    // encode GEMM (bf16 candidates): 128x128 tiles, 2 CTAs/SM
    gemm_enc_kernel<<<dim3(LATENT / BN, N_TOK / BM), 256, GEMM_SMEM>>>();

    // top-64 candidates per row
    topk_cand_kernel<<<N_TOK, 256>>>();

    // exact fp32 recompute + top-32 select + scatter into s
    exact_topk_kernel<<<N_TOK, 256>>>(x, W_enc, s);

    // sparse decode
    decode_kernel<<<N_TOK, 256>>>(xhat);
}

// round 5
// speedup vs baseline: 1.1280x; 1.0259x over previous
#include <cuda_runtime.h>
#include <cuda_bf16.h>
#include <cuda_fp16.h>
#include <stdint.h>

#define N_TOK   8192
#define HIDDEN  1024
#define LATENT  16384
#define TOPK    32
#define NCAND   64

// ---------------- static device scratch (no allocations allowed) ----------------
__device__ __half g_xh[(size_t)N_TOK * HIDDEN];     // 16 MB (fp16 x)
__device__ __half g_wh[(size_t)LATENT * HIDDEN];    // 32 MB (fp16 W_enc)
__device__ __half g_z [(size_t)N_TOK * LATENT];     // 256 MB
__device__ int    g_cand[(size_t)N_TOK * NCAND];    // 2 MB
__device__ int    g_tidx[(size_t)N_TOK * TOPK];
__device__ float  g_tval[(size_t)N_TOK * TOPK];
__device__ float  g_wdt[(size_t)LATENT * HIDDEN];   // 64 MB (W_dec transposed)

// ---------------- fp32 -> fp16 converts ----------------
__global__ void cvt_x_kernel(const float4* __restrict__ src, int n4) {
    int i = blockIdx.x * blockDim.x + threadIdx.x;
    if (i >= n4) return;
    float4 f = src[i];
    __half2 h0 = __floats2half2_rn(f.x, f.y);
    __half2 h1 = __floats2half2_rn(f.z, f.w);
    uint2 o; o.x = *(const uint32_t*)&h0; o.y = *(const uint32_t*)&h1;
    *(uint2*)&g_xh[(size_t)i * 4] = o;
}
__global__ void cvt_w_kernel(const float4* __restrict__ src, int n4) {
    int i = blockIdx.x * blockDim.x + threadIdx.x;
    if (i >= n4) return;
    float4 f = src[i];
    __half2 h0 = __floats2half2_rn(f.x, f.y);
    __half2 h1 = __floats2half2_rn(f.z, f.w);
    uint2 o; o.x = *(const uint32_t*)&h0; o.y = *(const uint32_t*)&h1;
    *(uint2*)&g_wh[(size_t)i * 4] = o;
}

// ---------------- encode GEMM: z = x @ W_enc^T (fp16 HMMA, fp16 accum, fp16 store) -----
// 128x256 CTA tile, 8 warps as 2x4 grid of 64x64 warp tiles, BK=64, 2-stage cp.async.
#define BM 128
#define BN 256
#define BK 64
#define KD HIDDEN
#define LDAS 72                          // 64 + 8 pad elems (144B rows, LDSM conflict-free)
#define NSTG 2
#define SA_ELEMS (BM * LDAS)             // 9216
#define SB_ELEMS (BN * LDAS)             // 18432
#define STG_ELEMS (SA_ELEMS + SB_ELEMS)  // 27648 halves = 55296 B/stage
#define GEMM_SMEM (NSTG * STG_ELEMS * 2) // 110592 B

__device__ __forceinline__ void cp_async16(uint32_t smem_dst, const void* gptr) {
    asm volatile("cp.async.cg.shared.global [%0], [%1], 16;"
                 :: "r"(smem_dst), "l"(gptr));
}
__device__ __forceinline__ void cp_commit() {
    asm volatile("cp.async.commit_group;");
}
template <int N>
__device__ __forceinline__ void cp_wait() {
    asm volatile("cp.async.wait_group %0;" :: "n"(N));
}

__global__ void __launch_bounds__(256, 2)
gemm_enc_kernel() {
    extern __shared__ __half sm[];

    const int tid  = threadIdx.x;
    const int lane = tid & 31;
    const int warp = tid >> 5;
    const int wr = warp >> 2;        // 0..1 -> 64 rows each
    const int wc = warp & 3;         // 0..3 -> 64 cols each
    const int bm = blockIdx.y * BM;
    const int bn = blockIdx.x * BN;

    // cp.async mapping: chunk idx = tid + 256*j ; row = idx>>3, col = (idx&7)*8
    const int gr = tid >> 3;             // base row 0..31 (each j adds 32)
    const int gc = (tid & 7) * 8;

    const __half* Ag = g_xh + (size_t)(bm + gr) * KD + gc;
    const __half* Bg = g_wh + (size_t)(bn + gr) * KD + gc;

    const uint32_t smemBase = (uint32_t)__cvta_generic_to_shared(sm);
    uint32_t dA[4], dB[8];
    #pragma unroll
    for (int j = 0; j < 4; ++j)
        dA[j] = (uint32_t)(((gr + 32 * j) * LDAS + gc) * 2);
    #pragma unroll
    for (int j = 0; j < 8; ++j)
        dB[j] = (uint32_t)((SA_ELEMS + (gr + 32 * j) * LDAS + gc) * 2);

    uint32_t acc[4][8][2];
    #pragma unroll
    for (int i = 0; i < 4; i++)
        #pragma unroll
        for (int j = 0; j < 8; j++) { acc[i][j][0] = 0u; acc[i][j][1] = 0u; }

    const int NKT = KD / BK;   // 16

    // prologue: stage 0
    {
        const uint32_t stg = smemBase;
        #pragma unroll
        for (int j = 0; j < 4; ++j) cp_async16(stg + dA[j], Ag + (size_t)(32 * j) * KD);
        #pragma unroll
        for (int j = 0; j < 8; ++j) cp_async16(stg + dB[j], Bg + (size_t)(32 * j) * KD);
        cp_commit();
    }

    for (int kt = 0; kt < NKT; ++kt) {
        cp_wait<0>();
        __syncthreads();          // stage kt fully visible to all warps

        // issue stage kt+1 into the other buffer (its readers finished at kt-1)
        if (kt + 1 < NKT) {
            const uint32_t stg = smemBase + ((kt + 1) & 1) * STG_ELEMS * 2;
            const int ko = (kt + 1) * BK;
            #pragma unroll
            for (int j = 0; j < 4; ++j) cp_async16(stg + dA[j], Ag + (size_t)(32 * j) * KD + ko);
            #pragma unroll
            for (int j = 0; j < 8; ++j) cp_async16(stg + dB[j], Bg + (size_t)(32 * j) * KD + ko);
            cp_commit();
        }

        const uint32_t cur = smemBase + (kt & 1) * STG_ELEMS * 2;
        const uint32_t aBase = cur;
        const uint32_t bBase = cur + SA_ELEMS * 2;

        #pragma unroll
        for (int ks = 0; ks < 4; ++ks) {
            const int kb = ks * 16;
            uint32_t afr[4][4];
            #pragma unroll
            for (int mi = 0; mi < 4; ++mi) {
                int row = wr * 64 + mi * 16 + (lane & 15);
                int col = kb + ((lane >> 4) << 3);
                uint32_t addr = aBase + (uint32_t)(row * LDAS + col) * 2;
                asm volatile("ldmatrix.sync.aligned.m8n8.x4.shared.b16 {%0,%1,%2,%3}, [%4];"
                    : "=r"(afr[mi][0]), "=r"(afr[mi][1]), "=r"(afr[mi][2]), "=r"(afr[mi][3])
                    : "r"(addr));
            }
            uint32_t bfr[8][2];
            #pragma unroll
            for (int j = 0; j < 4; ++j) {
                int n = wc * 64 + j * 16 + ((lane >> 4) << 3) + (lane & 7);
                int col = kb + (lane & 8);
                uint32_t addr = bBase + (uint32_t)(n * LDAS + col) * 2;
                asm volatile("ldmatrix.sync.aligned.m8n8.x4.shared.b16 {%0,%1,%2,%3}, [%4];"
                    : "=r"(bfr[2*j][0]), "=r"(bfr[2*j][1]), "=r"(bfr[2*j+1][0]), "=r"(bfr[2*j+1][1])
                    : "r"(addr));
            }
            #pragma unroll
            for (int mi = 0; mi < 4; ++mi)
                #pragma unroll
                for (int ni = 0; ni < 8; ++ni) {
                    asm volatile(
                        "mma.sync.aligned.m16n8k16.row.col.f16.f16.f16.f16 "
                        "{%0,%1},{%2,%3,%4,%5},{%6,%7},{%0,%1};"
                        : "+r"(acc[mi][ni][0]), "+r"(acc[mi][ni][1])
                        : "r"(afr[mi][0]), "r"(afr[mi][1]), "r"(afr[mi][2]), "r"(afr[mi][3]),
                          "r"(bfr[ni][0]), "r"(bfr[ni][1]));
                }
        }
        __syncthreads();          // all reads of buffer kt done before next overwrite
    }

    // epilogue: fp16 acc pairs stored directly
    const int grp = lane >> 2;
    const int qc  = (lane & 3) * 2;
    #pragma unroll
    for (int mi = 0; mi < 4; ++mi)
        #pragma unroll
        for (int ni = 0; ni < 8; ++ni) {
            int r0 = bm + wr * 64 + mi * 16 + grp;
            int c0 = bn + wc * 64 + ni * 8 + qc;
            *(uint32_t*)&g_z[(size_t)r0 * LATENT + c0] = acc[mi][ni][0];
            *(uint32_t*)&g_z[(size_t)(r0 + 8) * LATENT + c0] = acc[mi][ni][1];
        }
}

// ---------------- per-row top-64 candidates via 2-pass radix histogram on fp16 keys ----------------
__global__ void __launch_bounds__(256)
topk_cand_kernel() {
    __shared__ unsigned short keys[LATENT];          // 32 KB
    __shared__ unsigned int histw[8][256];           // per-warp histograms, 8 KB
    __shared__ unsigned int hist[256];
    __shared__ int s_b, s_k2;
    __shared__ unsigned int s_T;
    __shared__ int s_cnt;
    __shared__ int cand[NCAND];

    const int row = blockIdx.x;
    const int tid = threadIdx.x;
    const int warp = tid >> 5;
    for (int j = tid; j < 8 * 256; j += 256) ((unsigned int*)histw)[j] = 0;
    if (tid == 0) s_cnt = 0;
    __syncthreads();

    const uint4* zr = (const uint4*)(g_z + (size_t)row * LATENT);
    for (int i = tid; i < LATENT / 8; i += 256) {
        uint4 v = zr[i];
        uint32_t w[4] = {v.x, v.y, v.z, v.w};
        #pragma unroll
        for (int q = 0; q < 4; ++q) {
            #pragma unroll
            for (int p = 0; p < 2; ++p) {
                unsigned short h = (unsigned short)((w[q] >> (16 * p)) & 0xFFFFu);
                unsigned short key = (h & 0x8000u) ? (unsigned short)(~h)
                                                   : (unsigned short)(h | 0x8000u);
                keys[i * 8 + q * 2 + p] = key;
                atomicAdd(&histw[warp][key >> 8], 1u);
            }
        }
    }
    __syncthreads();
    if (tid < 256) {
        unsigned int c = 0;
        #pragma unroll
        for (int w = 0; w < 8; ++w) c += histw[w][tid];
        hist[tid] = c;
    }
    __syncthreads();
    if (tid == 0) {
        unsigned int c = 0; int b = 255;
        for (; b >= 0; --b) { c += hist[b]; if (c >= NCAND) break; }
        s_b  = b;
        s_k2 = NCAND - (int)(c - hist[b]);
    }
    __syncthreads();
    const int bsel = s_b, k2 = s_k2;
    if (tid < 256) hist[tid] = 0;
    __syncthreads();
    for (int i = tid; i < LATENT; i += 256) {
        unsigned short key = keys[i];
        if ((key >> 8) == (unsigned)bsel) atomicAdd(&hist[key & 255], 1u);
    }
    __syncthreads();
    if (tid == 0) {
        unsigned int c = 0; int l = 255;
        for (; l >= 0; --l) { c += hist[l]; if ((int)c >= k2) break; }
        s_T = ((unsigned)bsel << 8) | (unsigned)l;
    }
    __syncthreads();
    const unsigned int T = s_T;
    for (int i = tid; i < LATENT; i += 256) {
        if ((unsigned int)keys[i] > T) {
            int p = atomicAdd(&s_cnt, 1);
            cand[p] = i;
        }
    }
    __syncthreads();
    for (int i = tid; i < LATENT; i += 256) {
        if ((unsigned int)keys[i] == T) {
            int p = atomicAdd(&s_cnt, 1);
            if (p < NCAND) cand[p] = i;
        }
    }
    __syncthreads();
    if (tid < NCAND) g_cand[(size_t)row * NCAND + tid] = cand[tid];
}

// ---------------- exact fp32 recompute of 64 candidate dots + exact top-32 + scatter ----------------
__global__ void __launch_bounds__(256)
exact_topk_kernel(const float* __restrict__ x, const float* __restrict__ Wenc,
                  float* __restrict__ s_out) {
    __shared__ __align__(16) float xs[HIDDEN];
    __shared__ float vals[NCAND];
    __shared__ int   cand[NCAND];
    const int row  = blockIdx.x;
    const int tid  = threadIdx.x;
    const int lane = tid & 31;
    const int warp = tid >> 5;

    const float4* xr = (const float4*)(x + (size_t)row * HIDDEN);
    *(float4*)&xs[tid * 4] = xr[tid];
    if (tid < NCAND) cand[tid] = g_cand[(size_t)row * NCAND + tid];
    __syncthreads();

    for (int c = warp; c < NCAND; c += 8) {
        const float4* wrow = (const float4*)(Wenc + (size_t)cand[c] * HIDDEN);
        float a = 0.f;
        #pragma unroll
        for (int j = 0; j < 8; ++j) {
            float4 w4 = wrow[lane + 32 * j];
            float4 x4 = *(const float4*)&xs[(lane + 32 * j) * 4];
            a += w4.x * x4.x + w4.y * x4.y + w4.z * x4.z + w4.w * x4.w;
        }
        #pragma unroll
        for (int o = 16; o; o >>= 1) a += __shfl_xor_sync(0xffffffffu, a, o);
        if (lane == 0) vals[c] = a;
    }
    __syncthreads();

    if (warp == 0) {
        float v0 = vals[lane], v1 = vals[lane + 32];
        for (int t = 0; t < TOPK; ++t) {
            float lv = v0; int li = lane;
            if (v1 > lv) { lv = v1; li = lane + 32; }
            #pragma unroll
            for (int o = 16; o; o >>= 1) {
                float ov = __shfl_xor_sync(0xffffffffu, lv, o);
                int   oi = __shfl_xor_sync(0xffffffffu, li, o);
                if (ov > lv || (ov == lv && oi < li)) { lv = ov; li = oi; }
            }
            if (lane == 0) {
                int ci = cand[li];
                float rv = lv > 0.f ? lv : 0.f;
                s_out[(size_t)row * LATENT + ci] = rv;
                g_tidx[(size_t)row * TOPK + t] = ci;
                g_tval[(size_t)row * TOPK + t] = rv;
            }
            if ((li & 31) == lane) { if (li < 32) v0 = -1e30f; else v1 = -1e30f; }
        }
    }
}

// ---------------- W_dec transpose: [1024][16384] -> [16384][1024] ----------------
__global__ void transpose_wdec_kernel(const float* __restrict__ W) {
    __shared__ float t[32][33];
    const int bl = blockIdx.x * 32;   // latent
    const int bh = blockIdx.y * 32;   // hidden
    const int tx = threadIdx.x, ty = threadIdx.y;
    #pragma unroll
    for (int j = 0; j < 4; ++j)
        t[ty + 8 * j][tx] = W[(size_t)(bh + ty + 8 * j) * LATENT + bl + tx];
    __syncthreads();
    #pragma unroll
    for (int j = 0; j < 4; ++j)
        g_wdt[(size_t)(bl + ty + 8 * j) * HIDDEN + bh + tx] = t[tx][ty + 8 * j];
}

// ---------------- sparse decode: x_hat[n] = sum_k val_k * W_decT[idx_k] ----------------
__global__ void __launch_bounds__(256)
decode_kernel(float* __restrict__ xhat) {
    __shared__ int   sidx[TOPK];
    __shared__ float sval[TOPK];
    const int row = blockIdx.x;
    const int tid = threadIdx.x;
    if (tid < TOPK) {
        sidx[tid] = g_tidx[(size_t)row * TOPK + tid];
        sval[tid] = g_tval[(size_t)row * TOPK + tid];
    }
    __syncthreads();
    float a0 = 0.f, a1 = 0.f, a2 = 0.f, a3 = 0.f;
    #pragma unroll 4
    for (int k = 0; k < TOPK; ++k) {
        const float* wt = g_wdt + (size_t)sidx[k] * HIDDEN;
        float v = sval[k];
        a0 += v * wt[tid];
        a1 += v * wt[tid + 256];
        a2 += v * wt[tid + 512];
        a3 += v * wt[tid + 768];
    }
    float* o = xhat + (size_t)row * HIDDEN;
    o[tid] = a0; o[tid + 256] = a1; o[tid + 512] = a2; o[tid + 768] = a3;
}

// ---------------- launch ----------------
extern "C" void kernel_launch(void* const* d_in, const int* in_sizes, int n_in,
                              void* d_out, int out_size) {
    const float* x     = (const float*)d_in[0];
    const float* W_enc = (const float*)d_in[1];
    const float* W_dec = (const float*)d_in[2];
    float* xhat = (float*)d_out;
    float* s    = (float*)d_out + (size_t)N_TOK * HIDDEN;

    // lazy one-time handles (created on the uncaptured correctness call)
    static cudaStream_t side = nullptr;
    static cudaEvent_t efork = nullptr, ejoin = nullptr;
    if (!side) {
        cudaStreamCreateWithFlags(&side, cudaStreamNonBlocking);
        cudaEventCreateWithFlags(&efork, cudaEventDisableTiming);
        cudaEventCreateWithFlags(&ejoin, cudaEventDisableTiming);
        cudaFuncSetAttribute(gemm_enc_kernel,
                             cudaFuncAttributeMaxDynamicSharedMemorySize, GEMM_SMEM);
    }

    // fork: side stream does memset(s) + W_dec transpose, overlapping the GEMM
    cudaEventRecord(efork, 0);
    cudaStreamWaitEvent(side, efork, 0);
    cudaMemsetAsync(s, 0, (size_t)N_TOK * LATENT * sizeof(float), side);
    transpose_wdec_kernel<<<dim3(LATENT / 32, HIDDEN / 32), dim3(32, 8), 0, side>>>(W_dec);
    cudaEventRecord(ejoin, side);

    // main stream: converts -> GEMM -> candidates
    cvt_x_kernel<<<(N_TOK * HIDDEN / 4 + 255) / 256, 256>>>((const float4*)x, N_TOK * HIDDEN / 4);
    cvt_w_kernel<<<(LATENT * HIDDEN / 4 + 255) / 256, 256>>>((const float4*)W_enc, LATENT * HIDDEN / 4);
    gemm_enc_kernel<<<dim3(LATENT / BN, N_TOK / BM), 256, GEMM_SMEM>>>();
    topk_cand_kernel<<<N_TOK, 256>>>();

    // join: memset + transpose must be done before scatter/decode
    cudaStreamWaitEvent(0, ejoin, 0);

    exact_topk_kernel<<<N_TOK, 256>>>(x, W_enc, s);
    decode_kernel<<<N_TOK, 256>>>(xhat);
}

// round 6
// speedup vs baseline: 1.1504x; 1.0199x over previous
#include <cuda_runtime.h>
#include <cuda_bf16.h>
#include <cuda_fp16.h>
#include <stdint.h>

#define N_TOK   8192
#define HIDDEN  1024
#define LATENT  16384
#define TOPK    32
#define NCAND   64

// ---------------- static device scratch (no allocations allowed) ----------------
__device__ __half          g_xh[(size_t)N_TOK * HIDDEN];     // 16 MB (fp16 x)
__device__ __half          g_wh[(size_t)LATENT * HIDDEN];    // 32 MB (fp16 W_enc)
__device__ unsigned short  g_zk[(size_t)N_TOK * LATENT];     // 256 MB (order-preserving u16 keys)
__device__ int             g_cand[(size_t)N_TOK * NCAND];    // 2 MB
__device__ int             g_tidx[(size_t)N_TOK * TOPK];
__device__ float           g_tval[(size_t)N_TOK * TOPK];
__device__ float           g_wdt[(size_t)LATENT * HIDDEN];   // 64 MB (W_dec transposed)

// ---------------- fused fp32 -> fp16 convert (x and W_enc) ----------------
#define XN4 (N_TOK * HIDDEN / 4)
#define WN4 (LATENT * HIDDEN / 4)
__global__ void cvt_both_kernel(const float4* __restrict__ xs, const float4* __restrict__ ws) {
    int i = blockIdx.x * blockDim.x + threadIdx.x;
    if (i >= XN4 + WN4) return;
    float4 f;
    __half* dst;
    if (i < XN4) { f = xs[i]; dst = &g_xh[(size_t)i * 4]; }
    else         { f = ws[i - XN4]; dst = &g_wh[(size_t)(i - XN4) * 4]; }
    __half2 h0 = __floats2half2_rn(f.x, f.y);
    __half2 h1 = __floats2half2_rn(f.z, f.w);
    uint2 o; o.x = *(const uint32_t*)&h0; o.y = *(const uint32_t*)&h1;
    *(uint2*)dst = o;
}

// ---------------- encode GEMM: keys(x @ W_enc^T) (fp16 HMMA, fp16 accum) -----
// 128x256 CTA tile, 4 warps as 2x2 grid of 64x128 warp tiles, BK=64, 2-stage cp.async.
#define BM 128
#define BN 256
#define BK 64
#define KD HIDDEN
#define LDAS 72                          // 64 + 8 pad elems (144B rows, LDSM conflict-free)
#define NSTG 2
#define SA_ELEMS (BM * LDAS)             // 9216
#define SB_ELEMS (BN * LDAS)             // 18432
#define STG_ELEMS (SA_ELEMS + SB_ELEMS)  // 27648 halves = 55296 B/stage
#define GEMM_SMEM (NSTG * STG_ELEMS * 2) // 110592 B

__device__ __forceinline__ void cp_async16(uint32_t smem_dst, const void* gptr) {
    asm volatile("cp.async.cg.shared.global [%0], [%1], 16;"
                 :: "r"(smem_dst), "l"(gptr));
}
__device__ __forceinline__ void cp_commit() {
    asm volatile("cp.async.commit_group;");
}
template <int N>
__device__ __forceinline__ void cp_wait() {
    asm volatile("cp.async.wait_group %0;" :: "n"(N));
}
// fp16 pair -> order-preserving u16 key pair (neg: ~h, pos: h|0x8000), SIMD in u32
__device__ __forceinline__ uint32_t key2(uint32_t v) {
    uint32_t nn = (v >> 15) & 0x00010001u;
    return v ^ (0x80008000u | (nn * 0x7FFFu));
}

__global__ void __launch_bounds__(128, 2)
gemm_enc_kernel() {
    extern __shared__ __half sm[];

    const int tid  = threadIdx.x;
    const int lane = tid & 31;
    const int warp = tid >> 5;
    const int wr = warp >> 1;        // 0..1 -> 64 rows each
    const int wc = warp & 1;         // 0..1 -> 128 cols each
    const int bm = blockIdx.y * BM;
    const int bn = blockIdx.x * BN;

    // cp.async mapping: 128 threads; row = tid>>3 (+16 per j), col = (tid&7)*8
    const int gr = tid >> 3;             // 0..15
    const int gc = (tid & 7) * 8;

    const __half* Ag = g_xh + (size_t)(bm + gr) * KD + gc;
    const __half* Bg = g_wh + (size_t)(bn + gr) * KD + gc;

    const uint32_t smemBase = (uint32_t)__cvta_generic_to_shared(sm);
    const uint32_t dA0 = (uint32_t)((gr * LDAS + gc) * 2);
    const uint32_t dB0 = (uint32_t)((SA_ELEMS + gr * LDAS + gc) * 2);

    uint32_t acc[4][16][2];
    #pragma unroll
    for (int i = 0; i < 4; i++)
        #pragma unroll
        for (int j = 0; j < 16; j++) { acc[i][j][0] = 0u; acc[i][j][1] = 0u; }

    const int NKT = KD / BK;   // 16

    // prologue: stage 0
    {
        #pragma unroll
        for (int j = 0; j < 8; ++j)
            cp_async16(smemBase + dA0 + (uint32_t)(16 * j * LDAS * 2), Ag + (size_t)(16 * j) * KD);
        #pragma unroll
        for (int j = 0; j < 16; ++j)
            cp_async16(smemBase + dB0 + (uint32_t)(16 * j * LDAS * 2), Bg + (size_t)(16 * j) * KD);
        cp_commit();
    }

    for (int kt = 0; kt < NKT; ++kt) {
        cp_wait<0>();
        __syncthreads();          // stage kt visible; prior readers of the other buffer done

        if (kt + 1 < NKT) {
            const uint32_t stg = smemBase + ((kt + 1) & 1) * STG_ELEMS * 2;
            const int ko = (kt + 1) * BK;
            #pragma unroll
            for (int j = 0; j < 8; ++j)
                cp_async16(stg + dA0 + (uint32_t)(16 * j * LDAS * 2), Ag + (size_t)(16 * j) * KD + ko);
            #pragma unroll
            for (int j = 0; j < 16; ++j)
                cp_async16(stg + dB0 + (uint32_t)(16 * j * LDAS * 2), Bg + (size_t)(16 * j) * KD + ko);
            cp_commit();
        }

        const uint32_t cur = smemBase + (kt & 1) * STG_ELEMS * 2;
        const uint32_t aBase = cur;
        const uint32_t bBase = cur + SA_ELEMS * 2;

        #pragma unroll
        for (int ks = 0; ks < 4; ++ks) {
            const int kb = ks * 16;
            uint32_t afr[4][4];
            #pragma unroll
            for (int mi = 0; mi < 4; ++mi) {
                int row = wr * 64 + mi * 16 + (lane & 15);
                int col = kb + ((lane >> 4) << 3);
                uint32_t addr = aBase + (uint32_t)(row * LDAS + col) * 2;
                asm volatile("ldmatrix.sync.aligned.m8n8.x4.shared.b16 {%0,%1,%2,%3}, [%4];"
                    : "=r"(afr[mi][0]), "=r"(afr[mi][1]), "=r"(afr[mi][2]), "=r"(afr[mi][3])
                    : "r"(addr));
            }
            #pragma unroll
            for (int jb = 0; jb < 4; ++jb) {
                uint32_t bfr[4][2];
                #pragma unroll
                for (int j = 0; j < 2; ++j) {
                    int n = wc * 128 + jb * 32 + j * 16 + ((lane >> 4) << 3) + (lane & 7);
                    int col = kb + (lane & 8);
                    uint32_t addr = bBase + (uint32_t)(n * LDAS + col) * 2;
                    asm volatile("ldmatrix.sync.aligned.m8n8.x4.shared.b16 {%0,%1,%2,%3}, [%4];"
                        : "=r"(bfr[2*j][0]), "=r"(bfr[2*j][1]),
                          "=r"(bfr[2*j+1][0]), "=r"(bfr[2*j+1][1])
                        : "r"(addr));
                }
                #pragma unroll
                for (int mi = 0; mi < 4; ++mi)
                    #pragma unroll
                    for (int nj = 0; nj < 4; ++nj) {
                        const int ni = jb * 4 + nj;
                        asm volatile(
                            "mma.sync.aligned.m16n8k16.row.col.f16.f16.f16.f16 "
                            "{%0,%1},{%2,%3,%4,%5},{%6,%7},{%0,%1};"
                            : "+r"(acc[mi][ni][0]), "+r"(acc[mi][ni][1])
                            : "r"(afr[mi][0]), "r"(afr[mi][1]), "r"(afr[mi][2]), "r"(afr[mi][3]),
                              "r"(bfr[nj][0]), "r"(bfr[nj][1]));
                    }
            }
        }
    }

    // epilogue: fp16 acc -> order-preserving u16 keys
    const int grp = lane >> 2;
    const int qc  = (lane & 3) * 2;
    #pragma unroll
    for (int mi = 0; mi < 4; ++mi)
        #pragma unroll
        for (int ni = 0; ni < 16; ++ni) {
            int r0 = bm + wr * 64 + mi * 16 + grp;
            int c0 = bn + wc * 128 + ni * 8 + qc;
            *(uint32_t*)&g_zk[(size_t)r0 * LATENT + c0] = key2(acc[mi][ni][0]);
            *(uint32_t*)&g_zk[(size_t)(r0 + 8) * LATENT + c0] = key2(acc[mi][ni][1]);
        }
}

// ---------------- per-row top-64 candidates via 2-pass radix histogram on u16 keys ----------------
__global__ void __launch_bounds__(256)
topk_cand_kernel() {
    __shared__ unsigned short keys[LATENT];          // 32 KB
    __shared__ unsigned int histw[8][256];           // per-warp histograms, 8 KB
    __shared__ unsigned int hist[256];
    __shared__ int s_b, s_k2;
    __shared__ unsigned int s_T;
    __shared__ int s_cnt;
    __shared__ int cand[NCAND];

    const int row = blockIdx.x;
    const int tid = threadIdx.x;
    const int warp = tid >> 5;
    for (int j = tid; j < 8 * 256; j += 256) ((unsigned int*)histw)[j] = 0;
    if (tid == 0) s_cnt = 0;
    __syncthreads();

    const uint4* zr = (const uint4*)(g_zk + (size_t)row * LATENT);
    for (int i = tid; i < LATENT / 8; i += 256) {
        uint4 v = zr[i];
        uint32_t w[4] = {v.x, v.y, v.z, v.w};
        *(uint4*)&keys[i * 8] = v;
        #pragma unroll
        for (int q = 0; q < 4; ++q) {
            atomicAdd(&histw[warp][(w[q] >> 8) & 0xFFu], 1u);
            atomicAdd(&histw[warp][w[q] >> 24], 1u);
        }
    }
    __syncthreads();
    if (tid < 256) {
        unsigned int c = 0;
        #pragma unroll
        for (int w = 0; w < 8; ++w) c += histw[w][tid];
        hist[tid] = c;
    }
    __syncthreads();
    if (tid == 0) {
        unsigned int c = 0; int b = 255;
        for (; b >= 0; --b) { c += hist[b]; if (c >= NCAND) break; }
        s_b  = b;
        s_k2 = NCAND - (int)(c - hist[b]);
    }
    __syncthreads();
    const int bsel = s_b, k2 = s_k2;
    if (tid < 256) hist[tid] = 0;
    __syncthreads();
    for (int i = tid; i < LATENT; i += 256) {
        unsigned short key = keys[i];
        if ((key >> 8) == (unsigned)bsel) atomicAdd(&hist[key & 255], 1u);
    }
    __syncthreads();
    if (tid == 0) {
        unsigned int c = 0; int l = 255;
        for (; l >= 0; --l) { c += hist[l]; if ((int)c >= k2) break; }
        s_T = ((unsigned)bsel << 8) | (unsigned)l;
    }
    __syncthreads();
    const unsigned int T = s_T;
    for (int i = tid; i < LATENT; i += 256) {
        if ((unsigned int)keys[i] > T) {
            int p = atomicAdd(&s_cnt, 1);
            cand[p] = i;
        }
    }
    __syncthreads();
    for (int i = tid; i < LATENT; i += 256) {
        if ((unsigned int)keys[i] == T) {
            int p = atomicAdd(&s_cnt, 1);
            if (p < NCAND) cand[p] = i;
        }
    }
    __syncthreads();
    if (tid < NCAND) g_cand[(size_t)row * NCAND + tid] = cand[tid];
}

// ---------------- exact fp32 recompute of 64 candidate dots + exact top-32 + scatter ----------------
__global__ void __launch_bounds__(256)
exact_topk_kernel(const float* __restrict__ x, const float* __restrict__ Wenc,
                  float* __restrict__ s_out) {
    __shared__ __align__(16) float xs[HIDDEN];
    __shared__ float vals[NCAND];
    __shared__ int   cand[NCAND];
    const int row  = blockIdx.x;
    const int tid  = threadIdx.x;
    const int lane = tid & 31;
    const int warp = tid >> 5;

    const float4* xr = (const float4*)(x + (size_t)row * HIDDEN);
    *(float4*)&xs[tid * 4] = xr[tid];
    if (tid < NCAND) cand[tid] = g_cand[(size_t)row * NCAND + tid];
    __syncthreads();

    for (int c = warp; c < NCAND; c += 8) {
        const float4* wrow = (const float4*)(Wenc + (size_t)cand[c] * HIDDEN);
        float a = 0.f;
        #pragma unroll
        for (int j = 0; j < 8; ++j) {
            float4 w4 = wrow[lane + 32 * j];
            float4 x4 = *(const float4*)&xs[(lane + 32 * j) * 4];
            a += w4.x * x4.x + w4.y * x4.y + w4.z * x4.z + w4.w * x4.w;
        }
        #pragma unroll
        for (int o = 16; o; o >>= 1) a += __shfl_xor_sync(0xffffffffu, a, o);
        if (lane == 0) vals[c] = a;
    }
    __syncthreads();

    if (warp == 0) {
        float v0 = vals[lane], v1 = vals[lane + 32];
        for (int t = 0; t < TOPK; ++t) {
            float lv = v0; int li = lane;
            if (v1 > lv) { lv = v1; li = lane + 32; }
            #pragma unroll
            for (int o = 16; o; o >>= 1) {
                float ov = __shfl_xor_sync(0xffffffffu, lv, o);
                int   oi = __shfl_xor_sync(0xffffffffu, li, o);
                if (ov > lv || (ov == lv && oi < li)) { lv = ov; li = oi; }
            }
            if (lane == 0) {
                int ci = cand[li];
                float rv = lv > 0.f ? lv : 0.f;
                s_out[(size_t)row * LATENT + ci] = rv;
                g_tidx[(size_t)row * TOPK + t] = ci;
                g_tval[(size_t)row * TOPK + t] = rv;
            }
            if ((li & 31) == lane) { if (li < 32) v0 = -1e30f; else v1 = -1e30f; }
        }
    }
}

// ---------------- W_dec transpose: [1024][16384] -> [16384][1024] ----------------
__global__ void transpose_wdec_kernel(const float* __restrict__ W) {
    __shared__ float t[32][33];
    const int bl = blockIdx.x * 32;   // latent
    const int bh = blockIdx.y * 32;   // hidden
    const int tx = threadIdx.x, ty = threadIdx.y;
    #pragma unroll
    for (int j = 0; j < 4; ++j)
        t[ty + 8 * j][tx] = W[(size_t)(bh + ty + 8 * j) * LATENT + bl + tx];
    __syncthreads();
    #pragma unroll
    for (int j = 0; j < 4; ++j)
        g_wdt[(size_t)(bl + ty + 8 * j) * HIDDEN + bh + tx] = t[tx][ty + 8 * j];
}

// ---------------- sparse decode: x_hat[n] = sum_k val_k * W_decT[idx_k] ----------------
__global__ void __launch_bounds__(256)
decode_kernel(float* __restrict__ xhat) {
    __shared__ int   sidx[TOPK];
    __shared__ float sval[TOPK];
    const int row = blockIdx.x;
    const int tid = threadIdx.x;
    if (tid < TOPK) {
        sidx[tid] = g_tidx[(size_t)row * TOPK + tid];
        sval[tid] = g_tval[(size_t)row * TOPK + tid];
    }
    __syncthreads();
    float a0 = 0.f, a1 = 0.f, a2 = 0.f, a3 = 0.f;
    #pragma unroll 4
    for (int k = 0; k < TOPK; ++k) {
        const float* wt = g_wdt + (size_t)sidx[k] * HIDDEN;
        float v = sval[k];
        a0 += v * wt[tid];
        a1 += v * wt[tid + 256];
        a2 += v * wt[tid + 512];
        a3 += v * wt[tid + 768];
    }
    float* o = xhat + (size_t)row * HIDDEN;
    o[tid] = a0; o[tid + 256] = a1; o[tid + 512] = a2; o[tid + 768] = a3;
}

// ---------------- launch ----------------
extern "C" void kernel_launch(void* const* d_in, const int* in_sizes, int n_in,
                              void* d_out, int out_size) {
    const float* x     = (const float*)d_in[0];
    const float* W_enc = (const float*)d_in[1];
    const float* W_dec = (const float*)d_in[2];
    float* xhat = (float*)d_out;
    float* s    = (float*)d_out + (size_t)N_TOK * HIDDEN;

    // lazy one-time handles (created on the uncaptured correctness call)
    static cudaStream_t side = nullptr;
    static cudaEvent_t efork = nullptr, ejoin = nullptr;
    if (!side) {
        cudaStreamCreateWithFlags(&side, cudaStreamNonBlocking);
        cudaEventCreateWithFlags(&efork, cudaEventDisableTiming);
        cudaEventCreateWithFlags(&ejoin, cudaEventDisableTiming);
        cudaFuncSetAttribute(gemm_enc_kernel,
                             cudaFuncAttributeMaxDynamicSharedMemorySize, GEMM_SMEM);
    }

    // fork: side stream does memset(s) + W_dec transpose, overlapping the GEMM
    cudaEventRecord(efork, 0);
    cudaStreamWaitEvent(side, efork, 0);
    cudaMemsetAsync(s, 0, (size_t)N_TOK * LATENT * sizeof(float), side);
    transpose_wdec_kernel<<<dim3(LATENT / 32, HIDDEN / 32), dim3(32, 8), 0, side>>>(W_dec);
    cudaEventRecord(ejoin, side);

    // main stream: converts -> GEMM -> candidates
    cvt_both_kernel<<<(XN4 + WN4 + 255) / 256, 256>>>((const float4*)x, (const float4*)W_enc);
    gemm_enc_kernel<<<dim3(LATENT / BN, N_TOK / BM), 128, GEMM_SMEM>>>();
    topk_cand_kernel<<<N_TOK, 256>>>();

    // join: memset + transpose must be done before scatter/decode
    cudaStreamWaitEvent(0, ejoin, 0);

    exact_topk_kernel<<<N_TOK, 256>>>(x, W_enc, s);
    decode_kernel<<<N_TOK, 256>>>(xhat);
}